// round 11
// baseline (speedup 1.0000x reference)
#include <cuda_runtime.h>
#include <cstdint>

#define NMAX 100000
#define DD 64

static __device__ float g_k[NMAX * DD];
static __device__ float g_qv[NMAX * 2 * DD];   // per node: [q(64) | v(64)]
static __device__ float g_agg[NMAX * DD];

__device__ __forceinline__ void red_add_v4(float* p, float a, float b, float c, float d) {
    // no "memory" clobber: nothing in this kernel reads g_agg, and the
    // kernel boundary orders it for finalize. Lets ptxas overlap next
    // gather loads with outstanding REDs.
    asm volatile("red.global.add.v4.f32 [%0], {%1,%2,%3,%4};"
                 :: "l"(p), "f"(a), "f"(b), "f"(c), "f"(d));
}
__device__ __forceinline__ unsigned long long pack_dup(float v) {
    unsigned long long r;
    asm("mov.b64 %0, {%1, %2};" : "=l"(r) : "f"(v), "f"(v));
    return r;
}
__device__ __forceinline__ void ffma2(unsigned long long& d,
                                      unsigned long long a, unsigned long long b) {
    asm("fma.rn.f32x2 %0, %1, %2, %0;" : "+l"(d) : "l"(a), "l"(b));
}
__device__ __forceinline__ float2 unpack2(unsigned long long v) {
    float lo, hi;
    asm("mov.b64 {%0, %1}, %2;" : "=f"(lo), "=f"(hi) : "l"(v));
    return make_float2(lo, hi);
}

// ---------------------------------------------------------------------------
// K1 (validated ~104us): fused node projections.
// X[N,64] @ W4T[64,256], cols=[k|q|v|s]. 512 threads, 64 nodes/block.
// q and v are written interleaved into g_qv[N][128] for gather locality.
// ---------------------------------------------------------------------------
__global__ __launch_bounds__(512) void node_proj_kernel(
    const float* __restrict__ x,
    const float* __restrict__ Wk, const float* __restrict__ bk,
    const float* __restrict__ Wq, const float* __restrict__ bq,
    const float* __restrict__ Wv, const float* __restrict__ bv,
    const float* __restrict__ Ws, const float* __restrict__ bs,
    int n_nodes)
{
    extern __shared__ float sm[];
    float* w4  = sm;                 // [64][260]  w4[kk][m]
    float* xst = sm + 64 * 260;      // [64][68]   xst[kk][node]
    const int tid = threadIdx.x;

    const float* Wmat[4] = {Wk, Wq, Wv, Ws};
#pragma unroll
    for (int mat = 0; mat < 4; ++mat) {
        const float* W = Wmat[mat];
        for (int idx = tid; idx < 64 * 64; idx += 512) {
            int d = idx >> 6, kk = idx & 63;
            w4[kk * 260 + mat * 64 + d] = W[idx];
        }
    }
    const int nbase = blockIdx.x * 64;
    for (int idx = tid; idx < 64 * 16; idx += 512) {
        int j = idx >> 4, q = idx & 15;
        int n = nbase + j;
        float4 v = make_float4(0.f, 0.f, 0.f, 0.f);
        if (n < n_nodes) v = *(const float4*)&x[(size_t)n * 64 + q * 4];
        xst[(q * 4 + 0) * 68 + j] = v.x;
        xst[(q * 4 + 1) * 68 + j] = v.y;
        xst[(q * 4 + 2) * 68 + j] = v.z;
        xst[(q * 4 + 3) * 68 + j] = v.w;
    }
    __syncthreads();

    const int mg = tid >> 4;     // 0..31 -> m0 = mg*8
    const int ng = tid & 15;     // nodes ng*4 .. +3
    const int m0 = mg * 8;

    unsigned long long acc[4][4];
#pragma unroll
    for (int j = 0; j < 4; ++j)
#pragma unroll
        for (int p = 0; p < 4; ++p) acc[j][p] = 0ULL;

#pragma unroll 8
    for (int kk = 0; kk < 64; ++kk) {
        const ulonglong2 w01 = *(const ulonglong2*)&w4[kk * 260 + m0];
        const ulonglong2 w23 = *(const ulonglong2*)&w4[kk * 260 + m0 + 4];
        const float4 xv = *(const float4*)&xst[kk * 68 + ng * 4];
        unsigned long long xp[4] = {pack_dup(xv.x), pack_dup(xv.y),
                                    pack_dup(xv.z), pack_dup(xv.w)};
#pragma unroll
        for (int j = 0; j < 4; ++j) {
            ffma2(acc[j][0], w01.x, xp[j]);
            ffma2(acc[j][1], w01.y, xp[j]);
            ffma2(acc[j][2], w23.x, xp[j]);
            ffma2(acc[j][3], w23.y, xp[j]);
        }
    }

    const int mat = m0 >> 6;
    const int d0  = m0 & 63;
    const float* bmat[4] = {bk, bq, bv, bs};
    float bb[8];
#pragma unroll
    for (int i = 0; i < 8; ++i) bb[i] = bmat[mat][d0 + i];
    float* obase[4]      = {g_k, g_qv, g_qv + 64, g_agg};
    const int ostr[4]    = {64, 128, 128, 64};
    float* op = obase[mat];
    const int os = ostr[mat];

#pragma unroll
    for (int j = 0; j < 4; ++j) {
        int n = nbase + ng * 4 + j;
        if (n < n_nodes) {
            float2 a0 = unpack2(acc[j][0]), a1 = unpack2(acc[j][1]);
            float2 a2 = unpack2(acc[j][2]), a3 = unpack2(acc[j][3]);
            float4 r0 = make_float4(a0.x + bb[0], a0.y + bb[1], a1.x + bb[2], a1.y + bb[3]);
            float4 r1 = make_float4(a2.x + bb[4], a2.y + bb[5], a3.x + bb[6], a3.y + bb[7]);
            *(float4*)&op[(size_t)n * os + d0]     = r0;
            *(float4*)&op[(size_t)n * os + d0 + 4] = r1;
        }
    }
}

// ---------------------------------------------------------------------------
// K2 (R10 structure exact; gathers now 2 regions: k[dst] + qv[src] 512B):
// edge kernel, 256 threads, 128 edges/block.
// ---------------------------------------------------------------------------
__global__ __launch_bounds__(256) void edge_kernel(
    const float* __restrict__ edge_attr,
    const int* __restrict__ ei,             // [2, E] int32
    const float* __restrict__ We, const float* __restrict__ be,
    float* __restrict__ out_ea,
    int n_edges)
{
    extern __shared__ float sm[];
    float* wet  = sm;               // [64][68]  wet[kk][d]
    float* east = sm + 64 * 68;     // [64][132] east[kk][edge]
    __shared__ int s_src[128];
    __shared__ int s_dst[128];
    const int tid = threadIdx.x;

    for (int idx = tid; idx < 64 * 64; idx += 256) {
        int d = idx >> 6, kk = idx & 63;
        wet[kk * 68 + d] = We[idx];
    }
    const int ebase  = blockIdx.x * 128;
    const int ecount = min(128, n_edges - ebase);
    for (int idx = tid; idx < 128 * 16; idx += 256) {
        int j = idx >> 4, q = idx & 15;
        float4 v = make_float4(0.f, 0.f, 0.f, 0.f);
        if (j < ecount) {
            size_t g = (size_t)(ebase + j) * 64 + q * 4;
            v = __ldcs((const float4*)&edge_attr[g]);
            if (out_ea) __stcs((float4*)&out_ea[g], v);
        }
        east[(q * 4 + 0) * 132 + j] = v.x;
        east[(q * 4 + 1) * 132 + j] = v.y;
        east[(q * 4 + 2) * 132 + j] = v.z;
        east[(q * 4 + 3) * 132 + j] = v.w;
    }
    if (tid < 128 && tid < ecount) {
        s_src[tid] = ei[ebase + tid];
        s_dst[tid] = ei[(size_t)n_edges + ebase + tid];
    }
    __syncthreads();

    const int dg = tid & 7;    // d0 = dg*8
    const int eg = tid >> 3;   // edges eg*4 .. +3
    const int d0 = dg * 8;

    unsigned long long acc[4][4];
#pragma unroll
    for (int j = 0; j < 4; ++j)
#pragma unroll
        for (int p = 0; p < 4; ++p) acc[j][p] = 0ULL;

#pragma unroll 8
    for (int kk = 0; kk < 64; ++kk) {
        const ulonglong2 w01 = *(const ulonglong2*)&wet[kk * 68 + d0];
        const ulonglong2 w23 = *(const ulonglong2*)&wet[kk * 68 + d0 + 4];
        const float4 av = *(const float4*)&east[kk * 132 + eg * 4];
        unsigned long long ap[4] = {pack_dup(av.x), pack_dup(av.y),
                                    pack_dup(av.z), pack_dup(av.w)};
#pragma unroll
        for (int j = 0; j < 4; ++j) {
            ffma2(acc[j][0], w01.x, ap[j]);
            ffma2(acc[j][1], w01.y, ap[j]);
            ffma2(acc[j][2], w23.x, ap[j]);
            ffma2(acc[j][3], w23.y, ap[j]);
        }
    }

    float be8[8];
#pragma unroll
    for (int i = 0; i < 8; ++i) be8[i] = be[d0 + i];

#pragma unroll
    for (int j = 0; j < 4; ++j) {
        int e = eg * 4 + j;
        if (e < ecount) {
            const int src = s_src[e];
            const int dst = s_dst[e];
            const float* qvp = &g_qv[(size_t)src * 128];
            float kd[8], qs[8], vs[8];
            *(float4*)&kd[0] = *(const float4*)&g_k[(size_t)dst * 64 + d0];
            *(float4*)&kd[4] = *(const float4*)&g_k[(size_t)dst * 64 + d0 + 4];
            *(float4*)&qs[0] = *(const float4*)&qvp[d0];
            *(float4*)&qs[4] = *(const float4*)&qvp[d0 + 4];
            *(float4*)&vs[0] = *(const float4*)&qvp[64 + d0];
            *(float4*)&vs[4] = *(const float4*)&qvp[64 + d0 + 4];
            float ev8[8];
            float2 a0 = unpack2(acc[j][0]), a1 = unpack2(acc[j][1]);
            float2 a2 = unpack2(acc[j][2]), a3 = unpack2(acc[j][3]);
            ev8[0] = a0.x; ev8[1] = a0.y; ev8[2] = a1.x; ev8[3] = a1.y;
            ev8[4] = a2.x; ev8[5] = a2.y; ev8[6] = a3.x; ev8[7] = a3.y;
            float m[8];
#pragma unroll
            for (int i = 0; i < 8; ++i) {
                const float ev   = ev8[i] + be8[i];
                const float z    = kd[i] + qs[i] + 2.f * ev;
                const float gate = 1.f / (1.f + __expf(-z));
                m[i] = gate * (vs[i] + ev);
            }
            float* ap = &g_agg[(size_t)dst * 64 + d0];
            red_add_v4(ap,     m[0], m[1], m[2], m[3]);
            red_add_v4(ap + 4, m[4], m[5], m[6], m[7]);
        }
    }
}

// ---------------------------------------------------------------------------
// K3: out = relu(g_agg) (float4); copy u; cast edge_index -> float32.
// ---------------------------------------------------------------------------
__global__ __launch_bounds__(256) void finalize_kernel(
    float* __restrict__ out,
    const float* __restrict__ u,
    const int* __restrict__ ei,
    int n_nodes, int n_edges, int g_elems, int write_u, int write_ei)
{
    const size_t nd     = (size_t)n_nodes * 64;
    const size_t ed     = (size_t)n_edges * 64;
    const size_t stride = (size_t)gridDim.x * blockDim.x;
    const size_t t0     = (size_t)blockIdx.x * blockDim.x + threadIdx.x;

    const size_t nd4 = nd >> 2;
    const float4* agg4 = (const float4*)g_agg;
    float4* out4 = (float4*)out;
    for (size_t i = t0; i < nd4; i += stride) {
        float4 v = agg4[i];
        v.x = fmaxf(v.x, 0.f); v.y = fmaxf(v.y, 0.f);
        v.z = fmaxf(v.z, 0.f); v.w = fmaxf(v.w, 0.f);
        out4[i] = v;
    }

    if (write_u) {
        float* ou = out + nd + ed;
        for (size_t i = t0; i < (size_t)g_elems; i += stride)
            ou[i] = u[i];
    }
    if (write_ei) {
        float* oe = out + nd + ed + g_elems;
        const size_t ne2 = 2 * (size_t)n_edges;
        for (size_t i = t0; i < ne2; i += stride)
            oe[i] = (float)ei[i];
    }
}

extern "C" void kernel_launch(void* const* d_in, const int* in_sizes, int n_in,
                              void* d_out, int out_size) {
    const float* x  = (const float*)d_in[0];
    const int*   ei = (const int*)d_in[1];
    const float* ea = (const float*)d_in[2];
    const float* u  = (const float*)d_in[3];
    const float* Wk = (const float*)d_in[5];  const float* bk = (const float*)d_in[6];
    const float* Wq = (const float*)d_in[7];  const float* bq = (const float*)d_in[8];
    const float* Wv = (const float*)d_in[9];  const float* bv = (const float*)d_in[10];
    const float* We = (const float*)d_in[11]; const float* be = (const float*)d_in[12];
    const float* Ws = (const float*)d_in[13]; const float* bs = (const float*)d_in[14];

    const int n_nodes = in_sizes[0] / 64;
    const int n_edges = in_sizes[2] / 64;
    const int g_elems = in_sizes[3];
    float* out = (float*)d_out;

    const size_t nd = (size_t)n_nodes * 64;
    const size_t ed = (size_t)n_edges * 64;
    const int write_ea = ((size_t)out_size >= nd + ed);
    const int write_u  = ((size_t)out_size >= nd + ed + (size_t)g_elems);
    const int write_ei = ((size_t)out_size >= nd + ed + (size_t)g_elems + 2 * (size_t)n_edges);

    const int smem_node = (64 * 260 + 64 * 68) * 4;   // 83968 B
    const int smem_edge = (64 * 68 + 64 * 132) * 4;   // 51200 B
    cudaFuncSetAttribute(node_proj_kernel, cudaFuncAttributeMaxDynamicSharedMemorySize, smem_node);
    cudaFuncSetAttribute(edge_kernel,      cudaFuncAttributeMaxDynamicSharedMemorySize, smem_edge);

    const int nb1 = (n_nodes + 63) / 64;
    node_proj_kernel<<<nb1, 512, smem_node>>>(x, Wk, bk, Wq, bq, Wv, bv, Ws, bs, n_nodes);

    const int nb2 = (n_edges + 127) / 128;
    edge_kernel<<<nb2, 256, smem_edge>>>(ea, ei, We, be,
                                         write_ea ? out + nd : nullptr, n_edges);

    finalize_kernel<<<2048, 256>>>(out, u, ei, n_nodes, n_edges, g_elems, write_u, write_ei);
}

// round 14
// speedup vs baseline: 1.0252x; 1.0252x over previous
#include <cuda_runtime.h>
#include <cstdint>

#define NMAX 100000
#define DD 64

static __device__ float g_k[NMAX * DD];
static __device__ float g_q[NMAX * DD];
static __device__ float g_v[NMAX * DD];
static __device__ float g_agg[NMAX * DD];

__device__ __forceinline__ void red_add_v4(float* p, float a, float b, float c, float d) {
    asm volatile("red.global.add.v4.f32 [%0], {%1,%2,%3,%4};"
                 :: "l"(p), "f"(a), "f"(b), "f"(c), "f"(d) : "memory");
}
__device__ __forceinline__ unsigned long long pack_dup(float v) {
    unsigned long long r;
    asm("mov.b64 %0, {%1, %2};" : "=l"(r) : "f"(v), "f"(v));
    return r;
}
__device__ __forceinline__ void ffma2(unsigned long long& d,
                                      unsigned long long a, unsigned long long b) {
    asm("fma.rn.f32x2 %0, %1, %2, %0;" : "+l"(d) : "l"(a), "l"(b));
}
__device__ __forceinline__ float2 unpack2(unsigned long long v) {
    float lo, hi;
    asm("mov.b64 {%0, %1}, %2;" : "=f"(lo), "=f"(hi) : "l"(v));
    return make_float2(lo, hi);
}

// ---------------------------------------------------------------------------
// K1 (R8/R10-validated structure; ONE change: weight staging uses LDG.128).
// X[N,64] @ W4T[64,256], cols=[k|q|v|s]. 512 threads, 64 nodes/block.
// ---------------------------------------------------------------------------
__global__ __launch_bounds__(512) void node_proj_kernel(
    const float* __restrict__ x,
    const float* __restrict__ Wk, const float* __restrict__ bk,
    const float* __restrict__ Wq, const float* __restrict__ bq,
    const float* __restrict__ Wv, const float* __restrict__ bv,
    const float* __restrict__ Ws, const float* __restrict__ bs,
    int n_nodes)
{
    extern __shared__ float sm[];
    float* w4  = sm;                 // [64][260]  w4[kk][m]
    float* xst = sm + 64 * 260;      // [64][68]   xst[kk][node]
    const int tid = threadIdx.x;

    const float* Wmat[4] = {Wk, Wq, Wv, Ws};
#pragma unroll
    for (int mat = 0; mat < 4; ++mat) {
        const float* W = Wmat[mat];
        // 64x64 floats = 1024 float4 quads; vectorized global loads,
        // scalar transposed stores (same smem pattern as before).
        for (int idx = tid; idx < 1024; idx += 512) {
            int d = idx >> 4;           // 0..63
            int kk4 = (idx & 15) * 4;   // 0..60
            float4 w = *(const float4*)&W[d * 64 + kk4];
            w4[(kk4 + 0) * 260 + mat * 64 + d] = w.x;
            w4[(kk4 + 1) * 260 + mat * 64 + d] = w.y;
            w4[(kk4 + 2) * 260 + mat * 64 + d] = w.z;
            w4[(kk4 + 3) * 260 + mat * 64 + d] = w.w;
        }
    }
    const int nbase = blockIdx.x * 64;
    for (int idx = tid; idx < 64 * 16; idx += 512) {
        int j = idx >> 4, q = idx & 15;
        int n = nbase + j;
        float4 v = make_float4(0.f, 0.f, 0.f, 0.f);
        if (n < n_nodes) v = *(const float4*)&x[(size_t)n * 64 + q * 4];
        xst[(q * 4 + 0) * 68 + j] = v.x;
        xst[(q * 4 + 1) * 68 + j] = v.y;
        xst[(q * 4 + 2) * 68 + j] = v.z;
        xst[(q * 4 + 3) * 68 + j] = v.w;
    }
    __syncthreads();

    const int mg = tid >> 4;     // 0..31 -> m0 = mg*8
    const int ng = tid & 15;     // nodes ng*4 .. +3
    const int m0 = mg * 8;

    unsigned long long acc[4][4];
#pragma unroll
    for (int j = 0; j < 4; ++j)
#pragma unroll
        for (int p = 0; p < 4; ++p) acc[j][p] = 0ULL;

#pragma unroll 8
    for (int kk = 0; kk < 64; ++kk) {
        const ulonglong2 w01 = *(const ulonglong2*)&w4[kk * 260 + m0];
        const ulonglong2 w23 = *(const ulonglong2*)&w4[kk * 260 + m0 + 4];
        const float4 xv = *(const float4*)&xst[kk * 68 + ng * 4];
        unsigned long long xp[4] = {pack_dup(xv.x), pack_dup(xv.y),
                                    pack_dup(xv.z), pack_dup(xv.w)};
#pragma unroll
        for (int j = 0; j < 4; ++j) {
            ffma2(acc[j][0], w01.x, xp[j]);
            ffma2(acc[j][1], w01.y, xp[j]);
            ffma2(acc[j][2], w23.x, xp[j]);
            ffma2(acc[j][3], w23.y, xp[j]);
        }
    }

    const int mat = m0 >> 6;
    const int d0  = m0 & 63;
    const float* bmat[4] = {bk, bq, bv, bs};
    float bb[8];
#pragma unroll
    for (int i = 0; i < 8; ++i) bb[i] = bmat[mat][d0 + i];
    float* omat[4] = {g_k, g_q, g_v, g_agg};
    float* op = omat[mat];

#pragma unroll
    for (int j = 0; j < 4; ++j) {
        int n = nbase + ng * 4 + j;
        if (n < n_nodes) {
            float2 a0 = unpack2(acc[j][0]), a1 = unpack2(acc[j][1]);
            float2 a2 = unpack2(acc[j][2]), a3 = unpack2(acc[j][3]);
            float4 r0 = make_float4(a0.x + bb[0], a0.y + bb[1], a1.x + bb[2], a1.y + bb[3]);
            float4 r1 = make_float4(a2.x + bb[4], a2.y + bb[5], a3.x + bb[6], a3.y + bb[7]);
            *(float4*)&op[(size_t)n * 64 + d0]     = r0;
            *(float4*)&op[(size_t)n * 64 + d0 + 4] = r1;
        }
    }
}

// ---------------------------------------------------------------------------
// K2 (R10 exact; ONE change: We staging uses LDG.128):
// edge kernel, 256 threads, 128 edges/block.
// ---------------------------------------------------------------------------
__global__ __launch_bounds__(256) void edge_kernel(
    const float* __restrict__ edge_attr,
    const int* __restrict__ ei,             // [2, E] int32
    const float* __restrict__ We, const float* __restrict__ be,
    float* __restrict__ out_ea,
    int n_edges)
{
    extern __shared__ float sm[];
    float* wet  = sm;               // [64][68]  wet[kk][d]
    float* east = sm + 64 * 68;     // [64][132] east[kk][edge]
    __shared__ int s_src[128];
    __shared__ int s_dst[128];
    const int tid = threadIdx.x;

    // 64x64 = 1024 float4 quads; vectorized loads, scalar transposed stores.
    for (int idx = tid; idx < 1024; idx += 256) {
        int d = idx >> 4;           // 0..63
        int kk4 = (idx & 15) * 4;   // 0..60
        float4 w = *(const float4*)&We[d * 64 + kk4];
        wet[(kk4 + 0) * 68 + d] = w.x;
        wet[(kk4 + 1) * 68 + d] = w.y;
        wet[(kk4 + 2) * 68 + d] = w.z;
        wet[(kk4 + 3) * 68 + d] = w.w;
    }
    const int ebase  = blockIdx.x * 128;
    const int ecount = min(128, n_edges - ebase);
    for (int idx = tid; idx < 128 * 16; idx += 256) {
        int j = idx >> 4, q = idx & 15;
        float4 v = make_float4(0.f, 0.f, 0.f, 0.f);
        if (j < ecount) {
            size_t g = (size_t)(ebase + j) * 64 + q * 4;
            v = __ldcs((const float4*)&edge_attr[g]);
            if (out_ea) __stcs((float4*)&out_ea[g], v);
        }
        east[(q * 4 + 0) * 132 + j] = v.x;
        east[(q * 4 + 1) * 132 + j] = v.y;
        east[(q * 4 + 2) * 132 + j] = v.z;
        east[(q * 4 + 3) * 132 + j] = v.w;
    }
    if (tid < 128 && tid < ecount) {
        s_src[tid] = ei[ebase + tid];
        s_dst[tid] = ei[(size_t)n_edges + ebase + tid];
    }
    __syncthreads();

    const int dg = tid & 7;    // d0 = dg*8
    const int eg = tid >> 3;   // edges eg*4 .. +3
    const int d0 = dg * 8;

    unsigned long long acc[4][4];
#pragma unroll
    for (int j = 0; j < 4; ++j)
#pragma unroll
        for (int p = 0; p < 4; ++p) acc[j][p] = 0ULL;

#pragma unroll 8
    for (int kk = 0; kk < 64; ++kk) {
        const ulonglong2 w01 = *(const ulonglong2*)&wet[kk * 68 + d0];
        const ulonglong2 w23 = *(const ulonglong2*)&wet[kk * 68 + d0 + 4];
        const float4 av = *(const float4*)&east[kk * 132 + eg * 4];
        unsigned long long ap[4] = {pack_dup(av.x), pack_dup(av.y),
                                    pack_dup(av.z), pack_dup(av.w)};
#pragma unroll
        for (int j = 0; j < 4; ++j) {
            ffma2(acc[j][0], w01.x, ap[j]);
            ffma2(acc[j][1], w01.y, ap[j]);
            ffma2(acc[j][2], w23.x, ap[j]);
            ffma2(acc[j][3], w23.y, ap[j]);
        }
    }

    float be8[8];
#pragma unroll
    for (int i = 0; i < 8; ++i) be8[i] = be[d0 + i];

#pragma unroll
    for (int j = 0; j < 4; ++j) {
        int e = eg * 4 + j;
        if (e < ecount) {
            const int src = s_src[e];
            const int dst = s_dst[e];
            float kd[8], qs[8], vs[8];
            *(float4*)&kd[0] = *(const float4*)&g_k[(size_t)dst * 64 + d0];
            *(float4*)&kd[4] = *(const float4*)&g_k[(size_t)dst * 64 + d0 + 4];
            *(float4*)&qs[0] = *(const float4*)&g_q[(size_t)src * 64 + d0];
            *(float4*)&qs[4] = *(const float4*)&g_q[(size_t)src * 64 + d0 + 4];
            *(float4*)&vs[0] = *(const float4*)&g_v[(size_t)src * 64 + d0];
            *(float4*)&vs[4] = *(const float4*)&g_v[(size_t)src * 64 + d0 + 4];
            float ev8[8];
            float2 a0 = unpack2(acc[j][0]), a1 = unpack2(acc[j][1]);
            float2 a2 = unpack2(acc[j][2]), a3 = unpack2(acc[j][3]);
            ev8[0] = a0.x; ev8[1] = a0.y; ev8[2] = a1.x; ev8[3] = a1.y;
            ev8[4] = a2.x; ev8[5] = a2.y; ev8[6] = a3.x; ev8[7] = a3.y;
            float m[8];
#pragma unroll
            for (int i = 0; i < 8; ++i) {
                const float ev   = ev8[i] + be8[i];
                const float z    = kd[i] + qs[i] + 2.f * ev;
                const float gate = 1.f / (1.f + __expf(-z));
                m[i] = gate * (vs[i] + ev);
            }
            float* ap = &g_agg[(size_t)dst * 64 + d0];
            red_add_v4(ap,     m[0], m[1], m[2], m[3]);
            red_add_v4(ap + 4, m[4], m[5], m[6], m[7]);
        }
    }
}

// ---------------------------------------------------------------------------
// K3: out = relu(g_agg) (float4); copy u; cast edge_index -> float32.
// ---------------------------------------------------------------------------
__global__ __launch_bounds__(256) void finalize_kernel(
    float* __restrict__ out,
    const float* __restrict__ u,
    const int* __restrict__ ei,
    int n_nodes, int n_edges, int g_elems, int write_u, int write_ei)
{
    const size_t nd     = (size_t)n_nodes * 64;
    const size_t ed     = (size_t)n_edges * 64;
    const size_t stride = (size_t)gridDim.x * blockDim.x;
    const size_t t0     = (size_t)blockIdx.x * blockDim.x + threadIdx.x;

    const size_t nd4 = nd >> 2;
    const float4* agg4 = (const float4*)g_agg;
    float4* out4 = (float4*)out;
    for (size_t i = t0; i < nd4; i += stride) {
        float4 v = agg4[i];
        v.x = fmaxf(v.x, 0.f); v.y = fmaxf(v.y, 0.f);
        v.z = fmaxf(v.z, 0.f); v.w = fmaxf(v.w, 0.f);
        out4[i] = v;
    }

    if (write_u) {
        float* ou = out + nd + ed;
        for (size_t i = t0; i < (size_t)g_elems; i += stride)
            ou[i] = u[i];
    }
    if (write_ei) {
        float* oe = out + nd + ed + g_elems;
        const size_t ne2 = 2 * (size_t)n_edges;
        for (size_t i = t0; i < ne2; i += stride)
            oe[i] = (float)ei[i];
    }
}

extern "C" void kernel_launch(void* const* d_in, const int* in_sizes, int n_in,
                              void* d_out, int out_size) {
    const float* x  = (const float*)d_in[0];
    const int*   ei = (const int*)d_in[1];
    const float* ea = (const float*)d_in[2];
    const float* u  = (const float*)d_in[3];
    const float* Wk = (const float*)d_in[5];  const float* bk = (const float*)d_in[6];
    const float* Wq = (const float*)d_in[7];  const float* bq = (const float*)d_in[8];
    const float* Wv = (const float*)d_in[9];  const float* bv = (const float*)d_in[10];
    const float* We = (const float*)d_in[11]; const float* be = (const float*)d_in[12];
    const float* Ws = (const float*)d_in[13]; const float* bs = (const float*)d_in[14];

    const int n_nodes = in_sizes[0] / 64;
    const int n_edges = in_sizes[2] / 64;
    const int g_elems = in_sizes[3];
    float* out = (float*)d_out;

    const size_t nd = (size_t)n_nodes * 64;
    const size_t ed = (size_t)n_edges * 64;
    const int write_ea = ((size_t)out_size >= nd + ed);
    const int write_u  = ((size_t)out_size >= nd + ed + (size_t)g_elems);
    const int write_ei = ((size_t)out_size >= nd + ed + (size_t)g_elems + 2 * (size_t)n_edges);

    const int smem_node = (64 * 260 + 64 * 68) * 4;   // 83968 B
    const int smem_edge = (64 * 68 + 64 * 132) * 4;   // 51200 B
    cudaFuncSetAttribute(node_proj_kernel, cudaFuncAttributeMaxDynamicSharedMemorySize, smem_node);
    cudaFuncSetAttribute(edge_kernel,      cudaFuncAttributeMaxDynamicSharedMemorySize, smem_edge);

    const int nb1 = (n_nodes + 63) / 64;
    node_proj_kernel<<<nb1, 512, smem_node>>>(x, Wk, bk, Wq, bq, Wv, bv, Ws, bs, n_nodes);

    const int nb2 = (n_edges + 127) / 128;
    edge_kernel<<<nb2, 256, smem_edge>>>(ea, ei, We, be,
                                         write_ea ? out + nd : nullptr, n_edges);

    finalize_kernel<<<2048, 256>>>(out, u, ei, n_nodes, n_edges, g_elems, write_u, write_ei);
}

// round 16
// speedup vs baseline: 1.0643x; 1.0381x over previous
#include <cuda_runtime.h>
#include <cstdint>

#define NMAX 100000
#define DD 64

static __device__ float g_k[NMAX * DD];
static __device__ float g_q[NMAX * DD];
static __device__ float g_v[NMAX * DD];
static __device__ float g_agg[NMAX * DD];

__device__ __forceinline__ void red_add_v4(float* p, float a, float b, float c, float d) {
    asm volatile("red.global.add.v4.f32 [%0], {%1,%2,%3,%4};"
                 :: "l"(p), "f"(a), "f"(b), "f"(c), "f"(d) : "memory");
}
__device__ __forceinline__ unsigned long long pack_dup(float v) {
    unsigned long long r;
    asm("mov.b64 %0, {%1, %2};" : "=l"(r) : "f"(v), "f"(v));
    return r;
}
__device__ __forceinline__ void ffma2(unsigned long long& d,
                                      unsigned long long a, unsigned long long b) {
    asm("fma.rn.f32x2 %0, %1, %2, %0;" : "+l"(d) : "l"(a), "l"(b));
}
__device__ __forceinline__ float2 unpack2(unsigned long long v) {
    float lo, hi;
    asm("mov.b64 {%0, %1}, %2;" : "=f"(lo), "=f"(hi) : "l"(v));
    return make_float2(lo, hi);
}
// 32-byte evict_last gather: one LDG.256 keeps the hot k/q/v rows
// L2-resident against streaming traffic AND halves gather issue count.
// ptxas requires .v8.b32 (32B) for a direct .L2::evict_last qualifier.
__device__ __forceinline__ void ldg_el8(float* r, const float* p) {
    asm("ld.global.nc.L2::evict_last.v8.b32 {%0,%1,%2,%3,%4,%5,%6,%7}, [%8];"
        : "=f"(r[0]), "=f"(r[1]), "=f"(r[2]), "=f"(r[3]),
          "=f"(r[4]), "=f"(r[5]), "=f"(r[6]), "=f"(r[7])
        : "l"(p));
}

// ---------------------------------------------------------------------------
// K1 (R14-validated): fused node projections, LDG.128 weight staging.
// X[N,64] @ W4T[64,256], cols=[k|q|v|s]. 512 threads, 64 nodes/block.
// ---------------------------------------------------------------------------
__global__ __launch_bounds__(512) void node_proj_kernel(
    const float* __restrict__ x,
    const float* __restrict__ Wk, const float* __restrict__ bk,
    const float* __restrict__ Wq, const float* __restrict__ bq,
    const float* __restrict__ Wv, const float* __restrict__ bv,
    const float* __restrict__ Ws, const float* __restrict__ bs,
    int n_nodes)
{
    extern __shared__ float sm[];
    float* w4  = sm;                 // [64][260]  w4[kk][m]
    float* xst = sm + 64 * 260;      // [64][68]   xst[kk][node]
    const int tid = threadIdx.x;

    const float* Wmat[4] = {Wk, Wq, Wv, Ws};
#pragma unroll
    for (int mat = 0; mat < 4; ++mat) {
        const float* W = Wmat[mat];
        for (int idx = tid; idx < 1024; idx += 512) {
            int d = idx >> 4;           // 0..63
            int kk4 = (idx & 15) * 4;   // 0..60
            float4 w = *(const float4*)&W[d * 64 + kk4];
            w4[(kk4 + 0) * 260 + mat * 64 + d] = w.x;
            w4[(kk4 + 1) * 260 + mat * 64 + d] = w.y;
            w4[(kk4 + 2) * 260 + mat * 64 + d] = w.z;
            w4[(kk4 + 3) * 260 + mat * 64 + d] = w.w;
        }
    }
    const int nbase = blockIdx.x * 64;
    for (int idx = tid; idx < 64 * 16; idx += 512) {
        int j = idx >> 4, q = idx & 15;
        int n = nbase + j;
        float4 v = make_float4(0.f, 0.f, 0.f, 0.f);
        if (n < n_nodes) v = *(const float4*)&x[(size_t)n * 64 + q * 4];
        xst[(q * 4 + 0) * 68 + j] = v.x;
        xst[(q * 4 + 1) * 68 + j] = v.y;
        xst[(q * 4 + 2) * 68 + j] = v.z;
        xst[(q * 4 + 3) * 68 + j] = v.w;
    }
    __syncthreads();

    const int mg = tid >> 4;     // 0..31 -> m0 = mg*8
    const int ng = tid & 15;     // nodes ng*4 .. +3
    const int m0 = mg * 8;

    unsigned long long acc[4][4];
#pragma unroll
    for (int j = 0; j < 4; ++j)
#pragma unroll
        for (int p = 0; p < 4; ++p) acc[j][p] = 0ULL;

#pragma unroll 8
    for (int kk = 0; kk < 64; ++kk) {
        const ulonglong2 w01 = *(const ulonglong2*)&w4[kk * 260 + m0];
        const ulonglong2 w23 = *(const ulonglong2*)&w4[kk * 260 + m0 + 4];
        const float4 xv = *(const float4*)&xst[kk * 68 + ng * 4];
        unsigned long long xp[4] = {pack_dup(xv.x), pack_dup(xv.y),
                                    pack_dup(xv.z), pack_dup(xv.w)};
#pragma unroll
        for (int j = 0; j < 4; ++j) {
            ffma2(acc[j][0], w01.x, xp[j]);
            ffma2(acc[j][1], w01.y, xp[j]);
            ffma2(acc[j][2], w23.x, xp[j]);
            ffma2(acc[j][3], w23.y, xp[j]);
        }
    }

    const int mat = m0 >> 6;
    const int d0  = m0 & 63;
    const float* bmat[4] = {bk, bq, bv, bs};
    float bb[8];
#pragma unroll
    for (int i = 0; i < 8; ++i) bb[i] = bmat[mat][d0 + i];
    float* omat[4] = {g_k, g_q, g_v, g_agg};
    float* op = omat[mat];

#pragma unroll
    for (int j = 0; j < 4; ++j) {
        int n = nbase + ng * 4 + j;
        if (n < n_nodes) {
            float2 a0 = unpack2(acc[j][0]), a1 = unpack2(acc[j][1]);
            float2 a2 = unpack2(acc[j][2]), a3 = unpack2(acc[j][3]);
            float4 r0 = make_float4(a0.x + bb[0], a0.y + bb[1], a1.x + bb[2], a1.y + bb[3]);
            float4 r1 = make_float4(a2.x + bb[4], a2.y + bb[5], a3.x + bb[6], a3.y + bb[7]);
            *(float4*)&op[(size_t)n * 64 + d0]     = r0;
            *(float4*)&op[(size_t)n * 64 + d0 + 4] = r1;
        }
    }
}

// ---------------------------------------------------------------------------
// K2 (R14 exact; ONE concept changed: gathers are 32B evict_last loads):
// edge kernel, 256 threads, 128 edges/block.
// ---------------------------------------------------------------------------
__global__ __launch_bounds__(256) void edge_kernel(
    const float* __restrict__ edge_attr,
    const int* __restrict__ ei,             // [2, E] int32
    const float* __restrict__ We, const float* __restrict__ be,
    float* __restrict__ out_ea,
    int n_edges)
{
    extern __shared__ float sm[];
    float* wet  = sm;               // [64][68]  wet[kk][d]
    float* east = sm + 64 * 68;     // [64][132] east[kk][edge]
    __shared__ int s_src[128];
    __shared__ int s_dst[128];
    const int tid = threadIdx.x;

    for (int idx = tid; idx < 1024; idx += 256) {
        int d = idx >> 4;           // 0..63
        int kk4 = (idx & 15) * 4;   // 0..60
        float4 w = *(const float4*)&We[d * 64 + kk4];
        wet[(kk4 + 0) * 68 + d] = w.x;
        wet[(kk4 + 1) * 68 + d] = w.y;
        wet[(kk4 + 2) * 68 + d] = w.z;
        wet[(kk4 + 3) * 68 + d] = w.w;
    }
    const int ebase  = blockIdx.x * 128;
    const int ecount = min(128, n_edges - ebase);
    for (int idx = tid; idx < 128 * 16; idx += 256) {
        int j = idx >> 4, q = idx & 15;
        float4 v = make_float4(0.f, 0.f, 0.f, 0.f);
        if (j < ecount) {
            size_t g = (size_t)(ebase + j) * 64 + q * 4;
            v = __ldcs((const float4*)&edge_attr[g]);
            if (out_ea) __stcs((float4*)&out_ea[g], v);
        }
        east[(q * 4 + 0) * 132 + j] = v.x;
        east[(q * 4 + 1) * 132 + j] = v.y;
        east[(q * 4 + 2) * 132 + j] = v.z;
        east[(q * 4 + 3) * 132 + j] = v.w;
    }
    if (tid < 128 && tid < ecount) {
        s_src[tid] = ei[ebase + tid];
        s_dst[tid] = ei[(size_t)n_edges + ebase + tid];
    }
    __syncthreads();

    const int dg = tid & 7;    // d0 = dg*8
    const int eg = tid >> 3;   // edges eg*4 .. +3
    const int d0 = dg * 8;

    unsigned long long acc[4][4];
#pragma unroll
    for (int j = 0; j < 4; ++j)
#pragma unroll
        for (int p = 0; p < 4; ++p) acc[j][p] = 0ULL;

#pragma unroll 8
    for (int kk = 0; kk < 64; ++kk) {
        const ulonglong2 w01 = *(const ulonglong2*)&wet[kk * 68 + d0];
        const ulonglong2 w23 = *(const ulonglong2*)&wet[kk * 68 + d0 + 4];
        const float4 av = *(const float4*)&east[kk * 132 + eg * 4];
        unsigned long long ap[4] = {pack_dup(av.x), pack_dup(av.y),
                                    pack_dup(av.z), pack_dup(av.w)};
#pragma unroll
        for (int j = 0; j < 4; ++j) {
            ffma2(acc[j][0], w01.x, ap[j]);
            ffma2(acc[j][1], w01.y, ap[j]);
            ffma2(acc[j][2], w23.x, ap[j]);
            ffma2(acc[j][3], w23.y, ap[j]);
        }
    }

    float be8[8];
#pragma unroll
    for (int i = 0; i < 8; ++i) be8[i] = be[d0 + i];

#pragma unroll
    for (int j = 0; j < 4; ++j) {
        int e = eg * 4 + j;
        if (e < ecount) {
            const int src = s_src[e];
            const int dst = s_dst[e];
            float kd[8], qs[8], vs[8];
            ldg_el8(kd, &g_k[(size_t)dst * 64 + d0]);
            ldg_el8(qs, &g_q[(size_t)src * 64 + d0]);
            ldg_el8(vs, &g_v[(size_t)src * 64 + d0]);
            float ev8[8];
            float2 a0 = unpack2(acc[j][0]), a1 = unpack2(acc[j][1]);
            float2 a2 = unpack2(acc[j][2]), a3 = unpack2(acc[j][3]);
            ev8[0] = a0.x; ev8[1] = a0.y; ev8[2] = a1.x; ev8[3] = a1.y;
            ev8[4] = a2.x; ev8[5] = a2.y; ev8[6] = a3.x; ev8[7] = a3.y;
            float m[8];
#pragma unroll
            for (int i = 0; i < 8; ++i) {
                const float ev   = ev8[i] + be8[i];
                const float z    = kd[i] + qs[i] + 2.f * ev;
                const float gate = 1.f / (1.f + __expf(-z));
                m[i] = gate * (vs[i] + ev);
            }
            float* ap = &g_agg[(size_t)dst * 64 + d0];
            red_add_v4(ap,     m[0], m[1], m[2], m[3]);
            red_add_v4(ap + 4, m[4], m[5], m[6], m[7]);
        }
    }
}

// ---------------------------------------------------------------------------
// K3: out = relu(g_agg) (float4); copy u; cast edge_index -> float32.
// ---------------------------------------------------------------------------
__global__ __launch_bounds__(256) void finalize_kernel(
    float* __restrict__ out,
    const float* __restrict__ u,
    const int* __restrict__ ei,
    int n_nodes, int n_edges, int g_elems, int write_u, int write_ei)
{
    const size_t nd     = (size_t)n_nodes * 64;
    const size_t ed     = (size_t)n_edges * 64;
    const size_t stride = (size_t)gridDim.x * blockDim.x;
    const size_t t0     = (size_t)blockIdx.x * blockDim.x + threadIdx.x;

    const size_t nd4 = nd >> 2;
    const float4* agg4 = (const float4*)g_agg;
    float4* out4 = (float4*)out;
    for (size_t i = t0; i < nd4; i += stride) {
        float4 v = agg4[i];
        v.x = fmaxf(v.x, 0.f); v.y = fmaxf(v.y, 0.f);
        v.z = fmaxf(v.z, 0.f); v.w = fmaxf(v.w, 0.f);
        out4[i] = v;
    }

    if (write_u) {
        float* ou = out + nd + ed;
        for (size_t i = t0; i < (size_t)g_elems; i += stride)
            ou[i] = u[i];
    }
    if (write_ei) {
        float* oe = out + nd + ed + g_elems;
        const size_t ne2 = 2 * (size_t)n_edges;
        for (size_t i = t0; i < ne2; i += stride)
            oe[i] = (float)ei[i];
    }
}

extern "C" void kernel_launch(void* const* d_in, const int* in_sizes, int n_in,
                              void* d_out, int out_size) {
    const float* x  = (const float*)d_in[0];
    const int*   ei = (const int*)d_in[1];
    const float* ea = (const float*)d_in[2];
    const float* u  = (const float*)d_in[3];
    const float* Wk = (const float*)d_in[5];  const float* bk = (const float*)d_in[6];
    const float* Wq = (const float*)d_in[7];  const float* bq = (const float*)d_in[8];
    const float* Wv = (const float*)d_in[9];  const float* bv = (const float*)d_in[10];
    const float* We = (const float*)d_in[11]; const float* be = (const float*)d_in[12];
    const float* Ws = (const float*)d_in[13]; const float* bs = (const float*)d_in[14];

    const int n_nodes = in_sizes[0] / 64;
    const int n_edges = in_sizes[2] / 64;
    const int g_elems = in_sizes[3];
    float* out = (float*)d_out;

    const size_t nd = (size_t)n_nodes * 64;
    const size_t ed = (size_t)n_edges * 64;
    const int write_ea = ((size_t)out_size >= nd + ed);
    const int write_u  = ((size_t)out_size >= nd + ed + (size_t)g_elems);
    const int write_ei = ((size_t)out_size >= nd + ed + (size_t)g_elems + 2 * (size_t)n_edges);

    const int smem_node = (64 * 260 + 64 * 68) * 4;   // 83968 B
    const int smem_edge = (64 * 68 + 64 * 132) * 4;   // 51200 B
    cudaFuncSetAttribute(node_proj_kernel, cudaFuncAttributeMaxDynamicSharedMemorySize, smem_node);
    cudaFuncSetAttribute(edge_kernel,      cudaFuncAttributeMaxDynamicSharedMemorySize, smem_edge);

    const int nb1 = (n_nodes + 63) / 64;
    node_proj_kernel<<<nb1, 512, smem_node>>>(x, Wk, bk, Wq, bq, Wv, bv, Ws, bs, n_nodes);

    const int nb2 = (n_edges + 127) / 128;
    edge_kernel<<<nb2, 256, smem_edge>>>(ea, ei, We, be,
                                         write_ea ? out + nd : nullptr, n_edges);

    finalize_kernel<<<2048, 256>>>(out, u, ei, n_nodes, n_edges, g_elems, write_u, write_ei);
}

// round 17
// speedup vs baseline: 1.0838x; 1.0184x over previous
#include <cuda_runtime.h>
#include <cstdint>

#define NMAX 100000
#define DD 64

static __device__ float g_k[NMAX * DD];
static __device__ float g_q[NMAX * DD];
static __device__ float g_v[NMAX * DD];
static __device__ float g_agg[NMAX * DD];

__device__ __forceinline__ void red_add_v4(float* p, float a, float b, float c, float d) {
    asm volatile("red.global.add.v4.f32 [%0], {%1,%2,%3,%4};"
                 :: "l"(p), "f"(a), "f"(b), "f"(c), "f"(d) : "memory");
}
__device__ __forceinline__ unsigned long long pack_dup(float v) {
    unsigned long long r;
    asm("mov.b64 %0, {%1, %2};" : "=l"(r) : "f"(v), "f"(v));
    return r;
}
__device__ __forceinline__ void ffma2(unsigned long long& d,
                                      unsigned long long a, unsigned long long b) {
    asm("fma.rn.f32x2 %0, %1, %2, %0;" : "+l"(d) : "l"(a), "l"(b));
}
__device__ __forceinline__ float2 unpack2(unsigned long long v) {
    float lo, hi;
    asm("mov.b64 {%0, %1}, %2;" : "=f"(lo), "=f"(hi) : "l"(v));
    return make_float2(lo, hi);
}
// 32-byte evict_last gather (R16-validated): keeps hot k/q/v rows L2-resident
// and halves gather issue count. ptxas requires .v8.b32 for this qualifier.
__device__ __forceinline__ void ldg_el8(float* r, const float* p) {
    asm("ld.global.nc.L2::evict_last.v8.b32 {%0,%1,%2,%3,%4,%5,%6,%7}, [%8];"
        : "=f"(r[0]), "=f"(r[1]), "=f"(r[2]), "=f"(r[3]),
          "=f"(r[4]), "=f"(r[5]), "=f"(r[6]), "=f"(r[7])
        : "l"(p));
}

// ---------------------------------------------------------------------------
// K1 (R8-validated staging, 104.8us): fused node projections.
// X[N,64] @ W4T[64,256], cols=[k|q|v|s]. 512 threads, 64 nodes/block.
// Weight staging is the SCALAR form (measured faster than LDG.128 here).
// ---------------------------------------------------------------------------
__global__ __launch_bounds__(512) void node_proj_kernel(
    const float* __restrict__ x,
    const float* __restrict__ Wk, const float* __restrict__ bk,
    const float* __restrict__ Wq, const float* __restrict__ bq,
    const float* __restrict__ Wv, const float* __restrict__ bv,
    const float* __restrict__ Ws, const float* __restrict__ bs,
    int n_nodes)
{
    extern __shared__ float sm[];
    float* w4  = sm;                 // [64][260]  w4[kk][m]
    float* xst = sm + 64 * 260;      // [64][68]   xst[kk][node]
    const int tid = threadIdx.x;

    const float* Wmat[4] = {Wk, Wq, Wv, Ws};
#pragma unroll
    for (int mat = 0; mat < 4; ++mat) {
        const float* W = Wmat[mat];
        for (int idx = tid; idx < 64 * 64; idx += 512) {
            int d = idx >> 6, kk = idx & 63;
            w4[kk * 260 + mat * 64 + d] = W[idx];
        }
    }
    const int nbase = blockIdx.x * 64;
    for (int idx = tid; idx < 64 * 16; idx += 512) {
        int j = idx >> 4, q = idx & 15;
        int n = nbase + j;
        float4 v = make_float4(0.f, 0.f, 0.f, 0.f);
        if (n < n_nodes) v = *(const float4*)&x[(size_t)n * 64 + q * 4];
        xst[(q * 4 + 0) * 68 + j] = v.x;
        xst[(q * 4 + 1) * 68 + j] = v.y;
        xst[(q * 4 + 2) * 68 + j] = v.z;
        xst[(q * 4 + 3) * 68 + j] = v.w;
    }
    __syncthreads();

    const int mg = tid >> 4;     // 0..31 -> m0 = mg*8
    const int ng = tid & 15;     // nodes ng*4 .. +3
    const int m0 = mg * 8;

    unsigned long long acc[4][4];
#pragma unroll
    for (int j = 0; j < 4; ++j)
#pragma unroll
        for (int p = 0; p < 4; ++p) acc[j][p] = 0ULL;

#pragma unroll 8
    for (int kk = 0; kk < 64; ++kk) {
        const ulonglong2 w01 = *(const ulonglong2*)&w4[kk * 260 + m0];
        const ulonglong2 w23 = *(const ulonglong2*)&w4[kk * 260 + m0 + 4];
        const float4 xv = *(const float4*)&xst[kk * 68 + ng * 4];
        unsigned long long xp[4] = {pack_dup(xv.x), pack_dup(xv.y),
                                    pack_dup(xv.z), pack_dup(xv.w)};
#pragma unroll
        for (int j = 0; j < 4; ++j) {
            ffma2(acc[j][0], w01.x, xp[j]);
            ffma2(acc[j][1], w01.y, xp[j]);
            ffma2(acc[j][2], w23.x, xp[j]);
            ffma2(acc[j][3], w23.y, xp[j]);
        }
    }

    const int mat = m0 >> 6;
    const int d0  = m0 & 63;
    const float* bmat[4] = {bk, bq, bv, bs};
    float bb[8];
#pragma unroll
    for (int i = 0; i < 8; ++i) bb[i] = bmat[mat][d0 + i];
    float* omat[4] = {g_k, g_q, g_v, g_agg};
    float* op = omat[mat];

#pragma unroll
    for (int j = 0; j < 4; ++j) {
        int n = nbase + ng * 4 + j;
        if (n < n_nodes) {
            float2 a0 = unpack2(acc[j][0]), a1 = unpack2(acc[j][1]);
            float2 a2 = unpack2(acc[j][2]), a3 = unpack2(acc[j][3]);
            float4 r0 = make_float4(a0.x + bb[0], a0.y + bb[1], a1.x + bb[2], a1.y + bb[3]);
            float4 r1 = make_float4(a2.x + bb[4], a2.y + bb[5], a3.x + bb[6], a3.y + bb[7]);
            *(float4*)&op[(size_t)n * 64 + d0]     = r0;
            *(float4*)&op[(size_t)n * 64 + d0 + 4] = r1;
        }
    }
}

// ---------------------------------------------------------------------------
// K2 (R16 exact, unchanged): edge kernel, 256 threads, 128 edges/block.
// LDG.128 We staging + 32B evict_last gathers + RED scatter.
// ---------------------------------------------------------------------------
__global__ __launch_bounds__(256) void edge_kernel(
    const float* __restrict__ edge_attr,
    const int* __restrict__ ei,             // [2, E] int32
    const float* __restrict__ We, const float* __restrict__ be,
    float* __restrict__ out_ea,
    int n_edges)
{
    extern __shared__ float sm[];
    float* wet  = sm;               // [64][68]  wet[kk][d]
    float* east = sm + 64 * 68;     // [64][132] east[kk][edge]
    __shared__ int s_src[128];
    __shared__ int s_dst[128];
    const int tid = threadIdx.x;

    for (int idx = tid; idx < 1024; idx += 256) {
        int d = idx >> 4;           // 0..63
        int kk4 = (idx & 15) * 4;   // 0..60
        float4 w = *(const float4*)&We[d * 64 + kk4];
        wet[(kk4 + 0) * 68 + d] = w.x;
        wet[(kk4 + 1) * 68 + d] = w.y;
        wet[(kk4 + 2) * 68 + d] = w.z;
        wet[(kk4 + 3) * 68 + d] = w.w;
    }
    const int ebase  = blockIdx.x * 128;
    const int ecount = min(128, n_edges - ebase);
    for (int idx = tid; idx < 128 * 16; idx += 256) {
        int j = idx >> 4, q = idx & 15;
        float4 v = make_float4(0.f, 0.f, 0.f, 0.f);
        if (j < ecount) {
            size_t g = (size_t)(ebase + j) * 64 + q * 4;
            v = __ldcs((const float4*)&edge_attr[g]);
            if (out_ea) __stcs((float4*)&out_ea[g], v);
        }
        east[(q * 4 + 0) * 132 + j] = v.x;
        east[(q * 4 + 1) * 132 + j] = v.y;
        east[(q * 4 + 2) * 132 + j] = v.z;
        east[(q * 4 + 3) * 132 + j] = v.w;
    }
    if (tid < 128 && tid < ecount) {
        s_src[tid] = ei[ebase + tid];
        s_dst[tid] = ei[(size_t)n_edges + ebase + tid];
    }
    __syncthreads();

    const int dg = tid & 7;    // d0 = dg*8
    const int eg = tid >> 3;   // edges eg*4 .. +3
    const int d0 = dg * 8;

    unsigned long long acc[4][4];
#pragma unroll
    for (int j = 0; j < 4; ++j)
#pragma unroll
        for (int p = 0; p < 4; ++p) acc[j][p] = 0ULL;

#pragma unroll 8
    for (int kk = 0; kk < 64; ++kk) {
        const ulonglong2 w01 = *(const ulonglong2*)&wet[kk * 68 + d0];
        const ulonglong2 w23 = *(const ulonglong2*)&wet[kk * 68 + d0 + 4];
        const float4 av = *(const float4*)&east[kk * 132 + eg * 4];
        unsigned long long ap[4] = {pack_dup(av.x), pack_dup(av.y),
                                    pack_dup(av.z), pack_dup(av.w)};
#pragma unroll
        for (int j = 0; j < 4; ++j) {
            ffma2(acc[j][0], w01.x, ap[j]);
            ffma2(acc[j][1], w01.y, ap[j]);
            ffma2(acc[j][2], w23.x, ap[j]);
            ffma2(acc[j][3], w23.y, ap[j]);
        }
    }

    float be8[8];
#pragma unroll
    for (int i = 0; i < 8; ++i) be8[i] = be[d0 + i];

#pragma unroll
    for (int j = 0; j < 4; ++j) {
        int e = eg * 4 + j;
        if (e < ecount) {
            const int src = s_src[e];
            const int dst = s_dst[e];
            float kd[8], qs[8], vs[8];
            ldg_el8(kd, &g_k[(size_t)dst * 64 + d0]);
            ldg_el8(qs, &g_q[(size_t)src * 64 + d0]);
            ldg_el8(vs, &g_v[(size_t)src * 64 + d0]);
            float ev8[8];
            float2 a0 = unpack2(acc[j][0]), a1 = unpack2(acc[j][1]);
            float2 a2 = unpack2(acc[j][2]), a3 = unpack2(acc[j][3]);
            ev8[0] = a0.x; ev8[1] = a0.y; ev8[2] = a1.x; ev8[3] = a1.y;
            ev8[4] = a2.x; ev8[5] = a2.y; ev8[6] = a3.x; ev8[7] = a3.y;
            float m[8];
#pragma unroll
            for (int i = 0; i < 8; ++i) {
                const float ev   = ev8[i] + be8[i];
                const float z    = kd[i] + qs[i] + 2.f * ev;
                const float gate = 1.f / (1.f + __expf(-z));
                m[i] = gate * (vs[i] + ev);
            }
            float* ap = &g_agg[(size_t)dst * 64 + d0];
            red_add_v4(ap,     m[0], m[1], m[2], m[3]);
            red_add_v4(ap + 4, m[4], m[5], m[6], m[7]);
        }
    }
}

// ---------------------------------------------------------------------------
// K3: out = relu(g_agg) (float4); copy u; cast edge_index -> float32.
// ---------------------------------------------------------------------------
__global__ __launch_bounds__(256) void finalize_kernel(
    float* __restrict__ out,
    const float* __restrict__ u,
    const int* __restrict__ ei,
    int n_nodes, int n_edges, int g_elems, int write_u, int write_ei)
{
    const size_t nd     = (size_t)n_nodes * 64;
    const size_t ed     = (size_t)n_edges * 64;
    const size_t stride = (size_t)gridDim.x * blockDim.x;
    const size_t t0     = (size_t)blockIdx.x * blockDim.x + threadIdx.x;

    const size_t nd4 = nd >> 2;
    const float4* agg4 = (const float4*)g_agg;
    float4* out4 = (float4*)out;
    for (size_t i = t0; i < nd4; i += stride) {
        float4 v = agg4[i];
        v.x = fmaxf(v.x, 0.f); v.y = fmaxf(v.y, 0.f);
        v.z = fmaxf(v.z, 0.f); v.w = fmaxf(v.w, 0.f);
        out4[i] = v;
    }

    if (write_u) {
        float* ou = out + nd + ed;
        for (size_t i = t0; i < (size_t)g_elems; i += stride)
            ou[i] = u[i];
    }
    if (write_ei) {
        float* oe = out + nd + ed + g_elems;
        const size_t ne2 = 2 * (size_t)n_edges;
        for (size_t i = t0; i < ne2; i += stride)
            oe[i] = (float)ei[i];
    }
}

extern "C" void kernel_launch(void* const* d_in, const int* in_sizes, int n_in,
                              void* d_out, int out_size) {
    const float* x  = (const float*)d_in[0];
    const int*   ei = (const int*)d_in[1];
    const float* ea = (const float*)d_in[2];
    const float* u  = (const float*)d_in[3];
    const float* Wk = (const float*)d_in[5];  const float* bk = (const float*)d_in[6];
    const float* Wq = (const float*)d_in[7];  const float* bq = (const float*)d_in[8];
    const float* Wv = (const float*)d_in[9];  const float* bv = (const float*)d_in[10];
    const float* We = (const float*)d_in[11]; const float* be = (const float*)d_in[12];
    const float* Ws = (const float*)d_in[13]; const float* bs = (const float*)d_in[14];

    const int n_nodes = in_sizes[0] / 64;
    const int n_edges = in_sizes[2] / 64;
    const int g_elems = in_sizes[3];
    float* out = (float*)d_out;

    const size_t nd = (size_t)n_nodes * 64;
    const size_t ed = (size_t)n_edges * 64;
    const int write_ea = ((size_t)out_size >= nd + ed);
    const int write_u  = ((size_t)out_size >= nd + ed + (size_t)g_elems);
    const int write_ei = ((size_t)out_size >= nd + ed + (size_t)g_elems + 2 * (size_t)n_edges);

    const int smem_node = (64 * 260 + 64 * 68) * 4;   // 83968 B
    const int smem_edge = (64 * 68 + 64 * 132) * 4;   // 51200 B
    cudaFuncSetAttribute(node_proj_kernel, cudaFuncAttributeMaxDynamicSharedMemorySize, smem_node);
    cudaFuncSetAttribute(edge_kernel,      cudaFuncAttributeMaxDynamicSharedMemorySize, smem_edge);

    const int nb1 = (n_nodes + 63) / 64;
    node_proj_kernel<<<nb1, 512, smem_node>>>(x, Wk, bk, Wq, bq, Wv, bv, Ws, bs, n_nodes);

    const int nb2 = (n_edges + 127) / 128;
    edge_kernel<<<nb2, 256, smem_edge>>>(ea, ei, We, be,
                                         write_ea ? out + nd : nullptr, n_edges);

    finalize_kernel<<<2048, 256>>>(out, u, ei, n_nodes, n_edges, g_elems, write_u, write_ei);
}